// round 3
// baseline (speedup 1.0000x reference)
#include <cuda_runtime.h>
#include <math.h>

// Both kernels use the SAME grid (NCTA) and the SAME contiguous chunk->CTA
// mapping. Pass A reads chunks forward; pass B reads them backward, so pass B's
// first reads hit the L2-resident tail that pass A just finished reading.
#define NCTA 1184               // 148 SMs * 8 CTAs, one full wave
#define THREADS 256

__device__ float g_partials[NCTA];

__device__ __forceinline__ float block_reduce_max(float m) {
    #pragma unroll
    for (int o = 16; o > 0; o >>= 1)
        m = fmaxf(m, __shfl_xor_sync(0xffffffffu, m, o));
    __shared__ float sm[THREADS / 32];
    int lane = threadIdx.x & 31;
    int w = threadIdx.x >> 5;
    if (lane == 0) sm[w] = m;
    __syncthreads();
    if (w == 0) {
        m = (lane < (THREADS / 32)) ? sm[lane] : 0.0f;
        #pragma unroll
        for (int o = 16; o > 0; o >>= 1)
            m = fmaxf(m, __shfl_xor_sync(0xffffffffu, m, o));
    }
    return m;  // valid in warp 0
}

__device__ __forceinline__ float max4(float4 v) {
    return fmaxf(fmaxf(fabsf(v.x), fabsf(v.y)), fmaxf(fabsf(v.z), fabsf(v.w)));
}

// Per-CTA contiguous chunk bounds (in float4 units).
__device__ __forceinline__ void chunk_bounds(long long nvec, long long& base, long long& end) {
    long long chunk = (nvec + NCTA - 1) / NCTA;
    base = (long long)blockIdx.x * chunk;
    end  = base + chunk;
    if (end > nvec) end = nvec;
    if (base > nvec) base = nvec;
}

// Pass A: max |x| over chunk, reading FORWARD.
__global__ void __launch_bounds__(THREADS)
bq_max_reduce_kernel(const float4* __restrict__ x, long long nvec,
                     const float* __restrict__ xs, long long ntail_base, int ntail) {
    long long base, end;
    chunk_bounds(nvec, base, end);

    float m = 0.0f;
    long long i = base + threadIdx.x;
    const long long T = THREADS;
    for (; i + 3 * T < end; i += 4 * T) {
        float4 v0 = x[i];
        float4 v1 = x[i + T];
        float4 v2 = x[i + 2 * T];
        float4 v3 = x[i + 3 * T];
        m = fmaxf(m, fmaxf(fmaxf(max4(v0), max4(v1)), fmaxf(max4(v2), max4(v3))));
    }
    for (; i < end; i += T)
        m = fmaxf(m, max4(x[i]));

    if (blockIdx.x == 0 && threadIdx.x < (unsigned)ntail)
        m = fmaxf(m, fabsf(xs[ntail_base + threadIdx.x]));

    m = block_reduce_max(m);
    if (threadIdx.x == 0)
        g_partials[blockIdx.x] = m;
}

__device__ __forceinline__ float bq_quant_one(float v, float s, float inv_s) {
    v = (v >= 0.0f) ? fmaxf(v, 1e-10f) : fminf(v, -1e-10f);  // zeros -> +1e-10
    float i = rintf(v * s);                                   // half-to-even
    i = fminf(fmaxf(i, -128.0f), 127.0f);                     // clip to int8 range
    return i * inv_s;                                         // exact pow2 scale
}

__device__ __forceinline__ void stcs4(float4* p, float4 v) {
    asm volatile("st.global.cs.v4.f32 [%0], {%1,%2,%3,%4};"
                 :: "l"(p), "f"(v.x), "f"(v.y), "f"(v.z), "f"(v.w) : "memory");
}

__device__ __forceinline__ float4 quant4(float4 v, float s, float inv_s) {
    v.x = bq_quant_one(v.x, s, inv_s);
    v.y = bq_quant_one(v.y, s, inv_s);
    v.z = bq_quant_one(v.z, s, inv_s);
    v.w = bq_quant_one(v.w, s, inv_s);
    return v;
}

// Pass B: reduce partials (L2-resident) in prologue, then quantize the SAME
// chunk in REVERSE order -> first reads hit the tail pass A left hot in L2.
// Reverse indexing keeps warps on a single contiguous 512B segment.
__global__ void __launch_bounds__(THREADS)
bq_quantize_kernel(const float4* __restrict__ x, float4* __restrict__ y,
                   long long nvec,
                   const float* __restrict__ xs, float* __restrict__ ys,
                   long long ntail_base, int ntail) {
    __shared__ float s_sc[2];
    {
        float m = 0.0f;
        for (int p = threadIdx.x; p < NCTA; p += THREADS)
            m = fmaxf(m, g_partials[p]);
        m = block_reduce_max(m);
        if (threadIdx.x == 0) {
            float maxv = fmaxf(m, 1e-10f);  // the 1e-10 clamp can only raise tiny maxima
            float e = floorf(log2f(maxv));
            e = fminf(fmaxf(e, -128.0f), 127.0f);
            s_sc[0] = exp2f(-e + 6.0f);     // 2^(-e + (bits-2)), bits=8
            s_sc[1] = exp2f(e - 6.0f);
        }
    }
    __syncthreads();
    const float s = s_sc[0], inv_s = s_sc[1];

    long long base, end;
    chunk_bounds(nvec, base, end);
    const long long m_cnt = end - base;   // float4s in this chunk
    const long long T = THREADS;
    const long long last = end - 1;

    long long k = threadIdx.x;
    for (; k + 3 * T < m_cnt; k += 4 * T) {
        long long i0 = last - k;
        long long i1 = last - (k + T);
        long long i2 = last - (k + 2 * T);
        long long i3 = last - (k + 3 * T);
        float4 v0 = x[i0];
        float4 v1 = x[i1];
        float4 v2 = x[i2];
        float4 v3 = x[i3];
        stcs4(&y[i0], quant4(v0, s, inv_s));
        stcs4(&y[i1], quant4(v1, s, inv_s));
        stcs4(&y[i2], quant4(v2, s, inv_s));
        stcs4(&y[i3], quant4(v3, s, inv_s));
    }
    for (; k < m_cnt; k += T) {
        long long i = last - k;
        stcs4(&y[i], quant4(x[i], s, inv_s));
    }

    if (blockIdx.x == 0 && threadIdx.x < (unsigned)ntail)
        ys[ntail_base + threadIdx.x] =
            bq_quant_one(xs[ntail_base + threadIdx.x], s, inv_s);
}

extern "C" void kernel_launch(void* const* d_in, const int* in_sizes, int n_in,
                              void* d_out, int out_size) {
    const float* x = (const float*)d_in[0];
    float* y = (float*)d_out;
    long long n = (long long)in_sizes[0];
    long long nvec = n >> 2;
    long long ntail_base = nvec << 2;
    int ntail = (int)(n - ntail_base);

    bq_max_reduce_kernel<<<NCTA, THREADS>>>(
        (const float4*)x, nvec, x, ntail_base, ntail);

    bq_quantize_kernel<<<NCTA, THREADS>>>(
        (const float4*)x, (float4*)y, nvec, x, y, ntail_base, ntail);
}

// round 4
// speedup vs baseline: 1.0448x; 1.0448x over previous
#include <cuda_runtime.h>
#include <math.h>

// Best-measured pattern (R1): forward grid-stride streaming, 2368 CTAs.
// Reset kernel + atomics replaced by a write-always partials array
// (deterministic under graph replay, no third launch).
#define RED_BLOCKS 2368          // 148 SMs * 16 CTAs
#define THREADS 256

__device__ float g_partials[RED_BLOCKS];

__device__ __forceinline__ float block_reduce_max(float m) {
    #pragma unroll
    for (int o = 16; o > 0; o >>= 1)
        m = fmaxf(m, __shfl_xor_sync(0xffffffffu, m, o));
    __shared__ float sm[THREADS / 32];
    int lane = threadIdx.x & 31;
    int w = threadIdx.x >> 5;
    if (lane == 0) sm[w] = m;
    __syncthreads();
    if (w == 0) {
        m = (lane < (THREADS / 32)) ? sm[lane] : 0.0f;
        #pragma unroll
        for (int o = 16; o > 0; o >>= 1)
            m = fmaxf(m, __shfl_xor_sync(0xffffffffu, m, o));
    }
    return m;  // valid in warp 0
}

__device__ __forceinline__ float4 ldcs4(const float4* p) {
    float4 v;
    asm volatile("ld.global.cs.v4.f32 {%0,%1,%2,%3}, [%4];"
                 : "=f"(v.x), "=f"(v.y), "=f"(v.z), "=f"(v.w) : "l"(p));
    return v;
}

__device__ __forceinline__ void stcs4(float4* p, float4 v) {
    asm volatile("st.global.cs.v4.f32 [%0], {%1,%2,%3,%4};"
                 :: "l"(p), "f"(v.x), "f"(v.y), "f"(v.z), "f"(v.w) : "memory");
}

__device__ __forceinline__ float max4(float4 v) {
    return fmaxf(fmaxf(fabsf(v.x), fabsf(v.y)), fmaxf(fabsf(v.z), fabsf(v.w)));
}

// Pass A: global max|x|, forward grid-stride streaming.
__global__ void __launch_bounds__(THREADS)
bq_max_reduce_kernel(const float4* __restrict__ x, long long nvec,
                     const float* __restrict__ xs, long long ntail_base, int ntail) {
    float m = 0.0f;
    const long long stride = (long long)gridDim.x * THREADS;
    for (long long i = blockIdx.x * (long long)THREADS + threadIdx.x; i < nvec; i += stride)
        m = fmaxf(m, max4(ldcs4(&x[i])));

    if (blockIdx.x == 0 && threadIdx.x < (unsigned)ntail)
        m = fmaxf(m, fabsf(xs[ntail_base + threadIdx.x]));

    m = block_reduce_max(m);
    if (threadIdx.x == 0)
        g_partials[blockIdx.x] = m;
}

__device__ __forceinline__ float bq_quant_one(float v, float s, float inv_s) {
    v = (v >= 0.0f) ? fmaxf(v, 1e-10f) : fminf(v, -1e-10f);  // zeros -> +1e-10
    float i = rintf(v * s);                                   // half-to-even
    i = fminf(fmaxf(i, -128.0f), 127.0f);                     // clip to int8 range
    return i * inv_s;                                         // exact pow2 scale
}

__device__ __forceinline__ float4 quant4(float4 v, float s, float inv_s) {
    v.x = bq_quant_one(v.x, s, inv_s);
    v.y = bq_quant_one(v.y, s, inv_s);
    v.z = bq_quant_one(v.z, s, inv_s);
    v.w = bq_quant_one(v.w, s, inv_s);
    return v;
}

// Pass B: prologue reduces the (L2-resident) partials, then forward
// grid-stride quantize stream.
__global__ void __launch_bounds__(THREADS)
bq_quantize_kernel(const float4* __restrict__ x, float4* __restrict__ y,
                   long long nvec,
                   const float* __restrict__ xs, float* __restrict__ ys,
                   long long ntail_base, int ntail) {
    __shared__ float s_sc[2];
    {
        float m = 0.0f;
        for (int p = threadIdx.x; p < RED_BLOCKS; p += THREADS)
            m = fmaxf(m, g_partials[p]);
        m = block_reduce_max(m);
        if (threadIdx.x == 0) {
            float maxv = fmaxf(m, 1e-10f);  // the 1e-10 clamp can only raise tiny maxima
            float e = floorf(log2f(maxv));
            e = fminf(fmaxf(e, -128.0f), 127.0f);
            s_sc[0] = exp2f(-e + 6.0f);     // 2^(-e + (bits-2)), bits=8
            s_sc[1] = exp2f(e - 6.0f);
        }
    }
    __syncthreads();
    const float s = s_sc[0], inv_s = s_sc[1];

    const long long stride = (long long)gridDim.x * THREADS;
    for (long long i = blockIdx.x * (long long)THREADS + threadIdx.x; i < nvec; i += stride)
        stcs4(&y[i], quant4(ldcs4(&x[i]), s, inv_s));

    if (blockIdx.x == 0 && threadIdx.x < (unsigned)ntail)
        ys[ntail_base + threadIdx.x] =
            bq_quant_one(xs[ntail_base + threadIdx.x], s, inv_s);
}

extern "C" void kernel_launch(void* const* d_in, const int* in_sizes, int n_in,
                              void* d_out, int out_size) {
    const float* x = (const float*)d_in[0];
    float* y = (float*)d_out;
    long long n = (long long)in_sizes[0];
    long long nvec = n >> 2;
    long long ntail_base = nvec << 2;
    int ntail = (int)(n - ntail_base);

    bq_max_reduce_kernel<<<RED_BLOCKS, THREADS>>>(
        (const float4*)x, nvec, x, ntail_base, ntail);

    bq_quantize_kernel<<<RED_BLOCKS, THREADS>>>(
        (const float4*)x, (float4*)y, nvec, x, y, ntail_base, ntail);
}